// round 7
// baseline (speedup 1.0000x reference)
#include <cuda_runtime.h>
#include <cuda_bf16.h>
#include <float.h>

#define Bc   8
#define Lc   2048
#define IND  1024
#define Dc   64
#define Hc   2
#define DH   32
#define NNc  32
#define TI   16

// scratch (no allocations allowed -> __device__ globals)
__device__ float g_xa[Bc * Lc * Dc];
__device__ float g_xb[Bc * Lc * Dc];
__device__ float g_attn[Bc * Lc * Dc];
__device__ int   g_top[Bc * Lc * NNc];
__device__ float g_norm[Bc * Hc * Lc];
__device__ float g_maxn[Bc * Hc];

// ---------------------------------------------------------------------------
// Top-32 smallest dist per (b,i) row. Per-warp local top-32 over a 256-chunk
// (register-resident), then one-warp merge of 8*32 candidates. 1 barrier total.
// ---------------------------------------------------------------------------
__global__ void topk_kernel(const float* __restrict__ dist,
                            const float* __restrict__ mask,
                            int* __restrict__ top) {
    __shared__ float cv[256];
    __shared__ int   ci[256];
    int row = blockIdx.x;            // 0..B*L-1
    int b   = row / Lc;
    int t   = threadIdx.x, w = t >> 5, lane = t & 31;
    const float* dr = dist + (size_t)row * Lc;
    const float* mr = mask + b * Lc;

    float v[8]; int jx[8];
    #pragma unroll
    for (int q = 0; q < 8; q++) {
        int j = w * 256 + q * 32 + lane;
        float m = mr[j];
        v[q]  = (m > 0.f) ? dr[j] : 3.0f;   // masked -> rank after all unmasked
        jx[q] = j;
    }
    // per-warp: extract 32 smallest (value, then index) into candidates
    for (int k = 0; k < 32; k++) {
        float bv = v[0]; int bq = 0;
        #pragma unroll
        for (int q = 1; q < 8; q++)
            if (v[q] < bv || (v[q] == bv && jx[q] < jx[bq])) { bv = v[q]; bq = q; }
        int bj = jx[bq];
        float rv = bv; int rj = bj;
        #pragma unroll
        for (int o = 16; o; o >>= 1) {
            float ov = __shfl_xor_sync(0xffffffffu, rv, o);
            int   oj = __shfl_xor_sync(0xffffffffu, rj, o);
            if (ov < rv || (ov == rv && oj < rj)) { rv = ov; rj = oj; }
        }
        if (bj == rj) v[bq] = FLT_MAX;          // only the winning lane owns rj
        if (lane == 0) { cv[w * 32 + k] = rv; ci[w * 32 + k] = rj; }
    }
    __syncthreads();
    if (w == 0) {
        float v2[8]; int j2[8];
        #pragma unroll
        for (int q = 0; q < 8; q++) { v2[q] = cv[q * 32 + lane]; j2[q] = ci[q * 32 + lane]; }
        for (int k = 0; k < 32; k++) {
            float bv = v2[0]; int bq = 0;
            #pragma unroll
            for (int q = 1; q < 8; q++)
                if (v2[q] < bv || (v2[q] == bv && j2[q] < j2[bq])) { bv = v2[q]; bq = q; }
            int bj = j2[bq];
            float rv = bv; int rj = bj;
            #pragma unroll
            for (int o = 16; o; o >>= 1) {
                float ov = __shfl_xor_sync(0xffffffffu, rv, o);
                int   oj = __shfl_xor_sync(0xffffffffu, rj, o);
                if (ov < rv || (ov == rv && oj < rj)) { rv = ov; rj = oj; }
            }
            if (bj == rj) v2[bq] = FLT_MAX;
            if (lane == 0) top[(size_t)row * NNc + k] = rj;
        }
    }
}

// ---------------------------------------------------------------------------
// Fused front-end: LN(1024) -> @w_in -> leaky -> LN(64) -> @w_h -> leaky -> LN(64)
// ---------------------------------------------------------------------------
__global__ void mlp_kernel(const float* __restrict__ node,
                           const float* __restrict__ gin, const float* __restrict__ bin,
                           const float* __restrict__ w_in, const float* __restrict__ bias_in,
                           const float* __restrict__ g1, const float* __restrict__ b1,
                           const float* __restrict__ w_h, const float* __restrict__ bias_h,
                           const float* __restrict__ g2, const float* __restrict__ b2,
                           float* __restrict__ out) {
    __shared__ __align__(16) float xs[8][IND];   // 32 KB
    __shared__ float red[4][8][Dc];              // 8 KB
    __shared__ float h[8][Dc];                   // 2 KB

    int t = threadIdx.x;
    int w = t >> 5, lane = t & 31;
    size_t row0 = (size_t)blockIdx.x * 8;

    // input LN: warp per row
    {
        size_t row = row0 + w;
        const float* xr = node + row * IND;
        float vals[IND / 32];
        float s = 0.f;
        #pragma unroll
        for (int k = 0; k < IND / 32; k++) { float v = xr[lane + 32 * k]; vals[k] = v; s += v; }
        #pragma unroll
        for (int o = 16; o; o >>= 1) s += __shfl_xor_sync(0xffffffffu, s, o);
        float mean = s * (1.f / IND);
        float vs = 0.f;
        #pragma unroll
        for (int k = 0; k < IND / 32; k++) { float d = vals[k] - mean; vs += d * d; }
        #pragma unroll
        for (int o = 16; o; o >>= 1) vs += __shfl_xor_sync(0xffffffffu, vs, o);
        float rstd = rsqrtf(vs * (1.f / IND) + 1e-5f);
        #pragma unroll
        for (int k = 0; k < IND / 32; k++) {
            int i = lane + 32 * k;
            xs[w][i] = (vals[k] - mean) * rstd * gin[i] + bin[i];
        }
    }
    __syncthreads();

    // GEMM1: 1024 -> 64, float4 over i (LDS:FFMA = 1:4)
    {
        int o = t & 63, quad = t >> 6;
        float acc[8];
        #pragma unroll
        for (int r = 0; r < 8; r++) acc[r] = 0.f;
        int i0 = quad * 256;
        for (int i = i0; i < i0 + 256; i += 4) {
            float w0 = w_in[(i + 0) * Dc + o];
            float w1 = w_in[(i + 1) * Dc + o];
            float w2 = w_in[(i + 2) * Dc + o];
            float w3 = w_in[(i + 3) * Dc + o];
            #pragma unroll
            for (int r = 0; r < 8; r++) {
                float4 xv = *(const float4*)&xs[r][i];
                acc[r] += xv.x * w0 + xv.y * w1 + xv.z * w2 + xv.w * w3;
            }
        }
        #pragma unroll
        for (int r = 0; r < 8; r++) red[quad][r][o] = acc[r];
    }
    __syncthreads();
    for (int p = t; p < 8 * Dc; p += 256) {
        int r = p >> 6, o = p & 63;
        float v = red[0][r][o] + red[1][r][o] + red[2][r][o] + red[3][r][o] + bias_in[o];
        h[r][o] = v > 0.f ? v : 0.01f * v;
    }
    __syncthreads();

    // LN h1
    {
        float a = h[w][lane], c = h[w][lane + 32];
        float s = a + c;
        #pragma unroll
        for (int o = 16; o; o >>= 1) s += __shfl_xor_sync(0xffffffffu, s, o);
        float mean = s * (1.f / 64.f);
        float da = a - mean, dc = c - mean;
        float vv = da * da + dc * dc;
        #pragma unroll
        for (int o = 16; o; o >>= 1) vv += __shfl_xor_sync(0xffffffffu, vv, o);
        float rstd = rsqrtf(vv * (1.f / 64.f) + 1e-5f);
        h[w][lane]      = da * rstd * g1[lane] + b1[lane];
        h[w][lane + 32] = dc * rstd * g1[lane + 32] + b1[lane + 32];
    }
    __syncthreads();

    // GEMM2: 64 -> 64
    float h2tmp[2];
    #pragma unroll
    for (int pp = 0; pp < 2; pp++) {
        int p = t + pp * 256;
        int r = p >> 6, o = p & 63;
        float acc = bias_h[o];
        #pragma unroll
        for (int i = 0; i < Dc; i++) acc += h[r][i] * w_h[i * Dc + o];
        h2tmp[pp] = acc > 0.f ? acc : 0.01f * acc;
    }
    __syncthreads();
    #pragma unroll
    for (int pp = 0; pp < 2; pp++) {
        int p = t + pp * 256;
        h[p >> 6][p & 63] = h2tmp[pp];
    }
    __syncthreads();

    // LN h2 + store
    {
        float a = h[w][lane], c = h[w][lane + 32];
        float s = a + c;
        #pragma unroll
        for (int o = 16; o; o >>= 1) s += __shfl_xor_sync(0xffffffffu, s, o);
        float mean = s * (1.f / 64.f);
        float da = a - mean, dc = c - mean;
        float vv = da * da + dc * dc;
        #pragma unroll
        for (int o = 16; o; o >>= 1) vv += __shfl_xor_sync(0xffffffffu, vv, o);
        float rstd = rsqrtf(vv * (1.f / 64.f) + 1e-5f);
        size_t row = row0 + w;
        out[row * Dc + lane]      = da * rstd * g2[lane] + b2[lane];
        out[row * Dc + lane + 32] = dc * rstd * g2[lane + 32] + b2[lane + 32];
    }
}

// ---------------------------------------------------------------------------
// Per-head row norms + per-slice max norm (for softmax upper bound m-hat).
// ---------------------------------------------------------------------------
__global__ void norms_kernel(const float* __restrict__ x,
                             float* __restrict__ nrm, float* __restrict__ mx) {
    __shared__ float wmax[8];
    int slice = blockIdx.x;
    int b = slice >> 1, hh = slice & 1;
    const float* xb = x + (size_t)b * Lc * Dc + hh * DH;
    int t = threadIdx.x;
    float lm = 0.f;
    for (int q = 0; q < 8; q++) {
        int row = q * 256 + t;
        const float4* p = (const float4*)(xb + (size_t)row * Dc);
        float ss = 0.f;
        #pragma unroll
        for (int u = 0; u < 8; u++) {
            float4 v = p[u];
            ss += v.x * v.x + v.y * v.y + v.z * v.z + v.w * v.w;
        }
        float nr = sqrtf(ss);
        nrm[slice * Lc + row] = nr;
        lm = fmaxf(lm, nr);
    }
    #pragma unroll
    for (int o = 16; o; o >>= 1) lm = fmaxf(lm, __shfl_xor_sync(0xffffffffu, lm, o));
    if ((t & 31) == 0) wmax[t >> 5] = lm;
    __syncthreads();
    if (t == 0) {
        float m = wmax[0];
        #pragma unroll
        for (int u = 1; u < 8; u++) m = fmaxf(m, wmax[u]);
        mx[slice] = m;
    }
}

// ---------------------------------------------------------------------------
// Attention, single streaming pass. For row r: m-hat = |h_r| * max_j |h_j|
// bounds every score (mask term <= 0), so e_j = exp(s_j - mhat) is safe and
// all renormalization ratios are exact. Z accumulated online in registers;
// no score tile. Top-32 scores recomputed in pass 2 (32x32 MAC per row).
// out = (sum_top e_j * h_j) / (sum_top e + 1e-5 * Z)      [raw, pre-LN]
// ---------------------------------------------------------------------------
__global__ __launch_bounds__(256) void attn_kernel(
        const float* __restrict__ x,
        const float* __restrict__ mask,
        const int* __restrict__ top,
        const float* __restrict__ nrm,
        const float* __restrict__ mx,
        float* __restrict__ out) {
    __shared__ __align__(16) float hi[TI * DH];   // query tile
    __shared__ float mh_s[TI];
    __shared__ float zrow[TI];
    __shared__ float wred[8 * TI];

    int t = threadIdx.x;                 // 256
    int slice = blockIdx.y;              // b*H + h
    int b = slice >> 1, hh = slice & 1;
    int i0 = blockIdx.x * TI;
    const float* xb = x + (size_t)b * Lc * Dc + hh * DH;

    for (int p = t; p < TI * DH; p += 256)
        hi[p] = xb[(size_t)(i0 + (p >> 5)) * Dc + (p & 31)];
    if (t < TI) mh_s[t] = nrm[slice * Lc + i0 + t] * mx[slice];
    __syncthreads();

    float mh[TI];
    #pragma unroll
    for (int r = 0; r < TI; r++) mh[r] = mh_s[r];

    float z[TI];
    #pragma unroll
    for (int r = 0; r < TI; r++) z[r] = 0.f;

    // pass 1: streaming Z
    for (int jj = 0; jj < Lc / 256; jj++) {
        int j = jj * 256 + t;
        const float4* hj4 = (const float4*)(xb + (size_t)j * Dc);
        float4 aj[8];
        #pragma unroll
        for (int q = 0; q < 8; q++) aj[q] = hj4[q];
        float am = (1.f - mask[b * Lc + j]) * -10000.f;
        #pragma unroll
        for (int r = 0; r < TI; r++) {
            const float4* hir = (const float4*)(hi + r * DH);
            float acc = 0.f;
            #pragma unroll
            for (int q = 0; q < 8; q++) {
                float4 hv = hir[q];
                acc += hv.x * aj[q].x + hv.y * aj[q].y + hv.z * aj[q].z + hv.w * aj[q].w;
            }
            z[r] += __expf(acc + am - mh[r]);
        }
    }
    // block-reduce z per row
    #pragma unroll
    for (int r = 0; r < TI; r++) {
        #pragma unroll
        for (int o = 16; o; o >>= 1) z[r] += __shfl_xor_sync(0xffffffffu, z[r], o);
    }
    if ((t & 31) == 0) {
        #pragma unroll
        for (int r = 0; r < TI; r++) wred[(t >> 5) * TI + r] = z[r];
    }
    __syncthreads();
    if (t < TI) {
        float zz = 0.f;
        #pragma unroll
        for (int w2 = 0; w2 < 8; w2++) zz += wred[w2 * TI + t];
        zrow[t] = zz;
    }
    __syncthreads();

    // pass 2: sparse top-32. Warp w: rows 2w, 2w+1. Lane = neighbor (score) and
    // output dim (PV gather).
    int w = t >> 5, d = t & 31;
    #pragma unroll
    for (int rr = 0; rr < 2; rr++) {
        int r = 2 * w + rr;
        int i = i0 + r;
        int idx = top[((size_t)(b * Lc + i)) * NNc + d];
        const float4* nj = (const float4*)(xb + (size_t)idx * Dc);
        float4 bj[8];
        #pragma unroll
        for (int q = 0; q < 8; q++) bj[q] = nj[q];
        const float4* hir = (const float4*)(hi + r * DH);
        float s = 0.f;
        #pragma unroll
        for (int q = 0; q < 8; q++) {
            float4 hv = hir[q];
            s += hv.x * bj[q].x + hv.y * bj[q].y + hv.z * bj[q].z + hv.w * bj[q].w;
        }
        s += (1.f - mask[b * Lc + idx]) * -10000.f;
        float e = __expf(s - mh_s[r]);
        float st = e;
        #pragma unroll
        for (int o = 16; o; o >>= 1) st += __shfl_xor_sync(0xffffffffu, st, o);
        float denom = st + 1e-5f * zrow[r];
        float acc = 0.f;
        #pragma unroll
        for (int k = 0; k < 32; k++) {
            float ek = __shfl_sync(0xffffffffu, e, k);
            int   jk = __shfl_sync(0xffffffffu, idx, k);
            acc += ek * xb[(size_t)jk * Dc + d];
        }
        out[(size_t)(b * Lc + i) * Dc + hh * DH + d] = acc / denom;
    }
}

// ---------------------------------------------------------------------------
__global__ void ln_kernel(const float* __restrict__ in,
                          const float* __restrict__ g, const float* __restrict__ bt,
                          float* __restrict__ out) {
    int t = threadIdx.x, w = t >> 5, lane = t & 31;
    size_t row = (size_t)blockIdx.x * 8 + w;
    float a = in[row * Dc + lane], c = in[row * Dc + lane + 32];
    float s = a + c;
    #pragma unroll
    for (int o = 16; o; o >>= 1) s += __shfl_xor_sync(0xffffffffu, s, o);
    float mean = s * (1.f / 64.f);
    float da = a - mean, dc = c - mean;
    float vv = da * da + dc * dc;
    #pragma unroll
    for (int o = 16; o; o >>= 1) vv += __shfl_xor_sync(0xffffffffu, vv, o);
    float rstd = rsqrtf(vv * (1.f / 64.f) + 1e-5f);
    out[row * Dc + lane]      = da * rstd * g[lane] + bt[lane];
    out[row * Dc + lane + 32] = dc * rstd * g[lane + 32] + bt[lane + 32];
}

__global__ void ln_proj_kernel(const float* __restrict__ in,
                               const float* __restrict__ g, const float* __restrict__ bt,
                               const float* __restrict__ wo, const float* __restrict__ bo,
                               float* __restrict__ y) {
    int t = threadIdx.x, w = t >> 5, lane = t & 31;
    size_t row = (size_t)blockIdx.x * 8 + w;
    float a = in[row * Dc + lane], c = in[row * Dc + lane + 32];
    float s = a + c;
    #pragma unroll
    for (int o = 16; o; o >>= 1) s += __shfl_xor_sync(0xffffffffu, s, o);
    float mean = s * (1.f / 64.f);
    float da = a - mean, dc = c - mean;
    float vv = da * da + dc * dc;
    #pragma unroll
    for (int o = 16; o; o >>= 1) vv += __shfl_xor_sync(0xffffffffu, vv, o);
    float rstd = rsqrtf(vv * (1.f / 64.f) + 1e-5f);
    float na = da * rstd * g[lane] + bt[lane];
    float nc = dc * rstd * g[lane + 32] + bt[lane + 32];
    float contrib = na * wo[lane] + nc * wo[lane + 32];
    #pragma unroll
    for (int o = 16; o; o >>= 1) contrib += __shfl_xor_sync(0xffffffffu, contrib, o);
    if (lane == 0) y[row] = contrib + bo[0];
}

// ---------------------------------------------------------------------------
extern "C" void kernel_launch(void* const* d_in, const int* in_sizes, int n_in,
                              void* d_out, int out_size) {
    const float* node  = (const float*)d_in[0];
    const float* dist  = (const float*)d_in[2];
    const float* mask  = (const float*)d_in[3];
    const float* ln_in_g = (const float*)d_in[4];
    const float* ln_in_b = (const float*)d_in[5];
    const float* w_in    = (const float*)d_in[6];
    const float* b_in    = (const float*)d_in[7];
    const float* g1      = (const float*)d_in[8];
    const float* b1      = (const float*)d_in[9];
    const float* w_h     = (const float*)d_in[10];
    const float* b_h     = (const float*)d_in[11];
    const float* g2      = (const float*)d_in[12];
    const float* b2      = (const float*)d_in[13];
    const float* a0g     = (const float*)d_in[14];
    const float* a0b     = (const float*)d_in[15];
    const float* a1g     = (const float*)d_in[16];
    const float* a1b     = (const float*)d_in[17];
    const float* w_out   = (const float*)d_in[18];
    const float* b_out   = (const float*)d_in[19];
    float* y = (float*)d_out;

    void *pxa, *pxb, *pattn, *ptop, *pnrm, *pmx;
    cudaGetSymbolAddress(&pxa, g_xa);
    cudaGetSymbolAddress(&pxb, g_xb);
    cudaGetSymbolAddress(&pattn, g_attn);
    cudaGetSymbolAddress(&ptop, g_top);
    cudaGetSymbolAddress(&pnrm, g_norm);
    cudaGetSymbolAddress(&pmx, g_maxn);
    float* xa   = (float*)pxa;
    float* xb   = (float*)pxb;
    float* attn = (float*)pattn;
    int*   topi = (int*)ptop;
    float* nrm  = (float*)pnrm;
    float* mxn  = (float*)pmx;

    topk_kernel<<<Bc * Lc, 256>>>(dist, mask, topi);
    mlp_kernel<<<Bc * Lc / 8, 256>>>(node, ln_in_g, ln_in_b, w_in, b_in,
                                     g1, b1, w_h, b_h, g2, b2, xa);

    dim3 agrid(Lc / TI, Bc * Hc);
    norms_kernel<<<Bc * Hc, 256>>>(xa, nrm, mxn);
    attn_kernel<<<agrid, 256>>>(xa, mask, topi, nrm, mxn, attn);
    ln_kernel<<<Bc * Lc / 8, 256>>>(attn, a0g, a0b, xb);
    norms_kernel<<<Bc * Hc, 256>>>(xb, nrm, mxn);
    attn_kernel<<<agrid, 256>>>(xb, mask, topi, nrm, mxn, attn);
    ln_proj_kernel<<<Bc * Lc / 8, 256>>>(attn, a1g, a1b, w_out, b_out, y);
}